// round 1
// baseline (speedup 1.0000x reference)
#include <cuda_runtime.h>
#include <cstdint>

// Problem constants
#define TOKENS 2048
#define HIDDEN 2048
#define INTER  5632
#define NEXP   8
#define TOPK   2
#define NPAIR  (TOKENS * TOPK)   // 4096

// GEMM tiling
#define BM 64
#define BN 128
#define BK 32
#define AS_STRIDE 36    // 64x32 A tile, padded: bank = (4g+tg)%32 all-distinct
#define WS_STRIDE 136   // 32x128 W tile, padded: bank = (8tg+g)%32 all-distinct

// -------- persistent device scratch (static: no runtime allocation) --------
__device__ int   d_cnt[NEXP];
__device__ int   d_off[NEXP];
__device__ int   d_tok[NPAIR];
__device__ float d_wgt[NPAIR];
__device__ float d_hbuf[(size_t)NPAIR * INTER];   // 92.3 MB intermediate h = silu(gate)*up

// ---------------------------------------------------------------------------
// helpers
// ---------------------------------------------------------------------------
__device__ __forceinline__ uint32_t f2tf32(float f) {
    uint32_t u;
    asm("cvt.rna.tf32.f32 %0, %1;" : "=r"(u) : "f"(f));
    return u;
}

__device__ __forceinline__ void mma_tf32(float c[4], const uint32_t a[4],
                                         uint32_t b0, uint32_t b1) {
    asm volatile(
        "mma.sync.aligned.m16n8k8.row.col.f32.tf32.tf32.f32 "
        "{%0,%1,%2,%3}, {%4,%5,%6,%7}, {%8,%9}, {%0,%1,%2,%3};\n"
        : "+f"(c[0]), "+f"(c[1]), "+f"(c[2]), "+f"(c[3])
        : "r"(a[0]), "r"(a[1]), "r"(a[2]), "r"(a[3]), "r"(b0), "r"(b1));
}

// ---------------------------------------------------------------------------
// Routing: bucket 4096 (token, k) pairs by expert into compact lists.
// Single block; fully recomputes all state every call (graph-replay safe).
// ---------------------------------------------------------------------------
__global__ void route_kernel(const int* __restrict__ eidx,
                             const float* __restrict__ ew) {
    __shared__ int s_cnt[NEXP];
    __shared__ int s_off[NEXP];
    __shared__ int s_cur[NEXP];
    int t = threadIdx.x;
    if (t < NEXP) s_cnt[t] = 0;
    __syncthreads();
    for (int p = t; p < NPAIR; p += blockDim.x)
        atomicAdd(&s_cnt[eidx[p]], 1);
    __syncthreads();
    if (t == 0) {
        int o = 0;
        for (int e = 0; e < NEXP; e++) { s_off[e] = o; s_cur[e] = o; o += s_cnt[e]; }
    }
    __syncthreads();
    for (int p = t; p < NPAIR; p += blockDim.x) {
        int e = eidx[p];
        int pos = atomicAdd(&s_cur[e], 1);
        d_tok[pos] = p >> 1;          // token id (p = token*TOPK + k)
        d_wgt[pos] = ew[p];
    }
    if (t < NEXP) { d_cnt[t] = s_cnt[t]; d_off[t] = s_off[t]; }
}

// ---------------------------------------------------------------------------
// GEMM1: for each expert e, rows = gathered tokens:
//   gate = Xg @ W1[e], up = Xg @ W3[e], h = silu(gate)*up  -> d_hbuf
// Block tile: BM=64 x BN=128, 4 warps (2x2), warp tile 32x64.
// Gate and up share A fragments (W1 and W3 tiles both resident in smem).
// Grid: (m_tile FASTEST for L2 W-slab reuse, n_tile, expert)
// ---------------------------------------------------------------------------
__global__ __launch_bounds__(128)
void gemm1_kernel(const float* __restrict__ x,
                  const float* __restrict__ w1,
                  const float* __restrict__ w3) {
    const int e   = blockIdx.z;
    const int cnt = d_cnt[e];
    const int m0  = blockIdx.x * BM;
    if (m0 >= cnt) return;
    const int n0  = blockIdx.y * BN;
    const int off = d_off[e];

    __shared__ uint32_t As [BM * AS_STRIDE];
    __shared__ uint32_t W1s[BK * WS_STRIDE];
    __shared__ uint32_t W3s[BK * WS_STRIDE];

    const int tid  = threadIdx.x;
    const int lane = tid & 31, warp = tid >> 5;
    const int wm = warp >> 1, wn = warp & 1;
    const int g = lane >> 2, tg = lane & 3;

    // Per-thread A-load row pointers (4 float4 loads per tile)
    const float* aptr[4];
#pragma unroll
    for (int i = 0; i < 4; i++) {
        int f = tid + i * 128;
        int row = f >> 3;
        int gr = m0 + row;
        aptr[i] = (gr < cnt) ? (x + (size_t)d_tok[off + gr] * HIDDEN) : nullptr;
    }
    const float* w1p = w1 + (size_t)e * HIDDEN * INTER + n0;
    const float* w3p = w3 + (size_t)e * HIDDEN * INTER + n0;

    float gacc[2][8][4];
    float uacc[2][8][4];
#pragma unroll
    for (int mi = 0; mi < 2; mi++)
#pragma unroll
        for (int ni = 0; ni < 8; ni++)
#pragma unroll
            for (int r = 0; r < 4; r++) { gacc[mi][ni][r] = 0.f; uacc[mi][ni][r] = 0.f; }

    for (int k0 = 0; k0 < HIDDEN; k0 += BK) {
        // ---- A tile: 64x32 fp32 -> tf32 ----
#pragma unroll
        for (int i = 0; i < 4; i++) {
            int f = tid + i * 128;
            int row = f >> 3, col = (f & 7) * 4;
            float4 v = make_float4(0.f, 0.f, 0.f, 0.f);
            if (aptr[i]) v = *(const float4*)(aptr[i] + k0 + col);
            uint32_t* dst = &As[row * AS_STRIDE + col];
            dst[0] = f2tf32(v.x); dst[1] = f2tf32(v.y);
            dst[2] = f2tf32(v.z); dst[3] = f2tf32(v.w);
        }
        // ---- W1/W3 tiles: 32x128 fp32 -> tf32 ----
#pragma unroll
        for (int i = 0; i < 8; i++) {
            int f = tid + i * 128;
            int row = f >> 5, col = (f & 31) * 4;
            const float4 v1 = *(const float4*)(w1p + (size_t)(k0 + row) * INTER + col);
            const float4 v3 = *(const float4*)(w3p + (size_t)(k0 + row) * INTER + col);
            uint32_t* d1 = &W1s[row * WS_STRIDE + col];
            d1[0] = f2tf32(v1.x); d1[1] = f2tf32(v1.y);
            d1[2] = f2tf32(v1.z); d1[3] = f2tf32(v1.w);
            uint32_t* d3 = &W3s[row * WS_STRIDE + col];
            d3[0] = f2tf32(v3.x); d3[1] = f2tf32(v3.y);
            d3[2] = f2tf32(v3.z); d3[3] = f2tf32(v3.w);
        }
        __syncthreads();

#pragma unroll
        for (int kk = 0; kk < BK; kk += 8) {
            uint32_t a[2][4];
#pragma unroll
            for (int mi = 0; mi < 2; mi++) {
                int rb = wm * 32 + mi * 16;
                a[mi][0] = As[(rb + g)     * AS_STRIDE + kk + tg];
                a[mi][1] = As[(rb + g + 8) * AS_STRIDE + kk + tg];
                a[mi][2] = As[(rb + g)     * AS_STRIDE + kk + tg + 4];
                a[mi][3] = As[(rb + g + 8) * AS_STRIDE + kk + tg + 4];
            }
#pragma unroll
            for (int ni = 0; ni < 8; ni++) {
                int cb = wn * 64 + ni * 8;
                uint32_t b0 = W1s[(kk + tg)     * WS_STRIDE + cb + g];
                uint32_t b1 = W1s[(kk + tg + 4) * WS_STRIDE + cb + g];
                uint32_t c0 = W3s[(kk + tg)     * WS_STRIDE + cb + g];
                uint32_t c1 = W3s[(kk + tg + 4) * WS_STRIDE + cb + g];
                mma_tf32(gacc[0][ni], a[0], b0, b1);
                mma_tf32(gacc[1][ni], a[1], b0, b1);
                mma_tf32(uacc[0][ni], a[0], c0, c1);
                mma_tf32(uacc[1][ni], a[1], c0, c1);
            }
        }
        __syncthreads();
    }

    // ---- epilogue: h = silu(gate)*up -> d_hbuf ----
#pragma unroll
    for (int mi = 0; mi < 2; mi++) {
#pragma unroll
        for (int ni = 0; ni < 8; ni++) {
            int lr0 = wm * 32 + mi * 16 + g;
            int lr1 = lr0 + 8;
            int col = n0 + wn * 64 + ni * 8 + tg * 2;
            if (m0 + lr0 < cnt) {
                float g0 = gacc[mi][ni][0], g1 = gacc[mi][ni][1];
                float h0 = g0 / (1.f + __expf(-g0)) * uacc[mi][ni][0];
                float h1 = g1 / (1.f + __expf(-g1)) * uacc[mi][ni][1];
                *(float2*)(d_hbuf + (size_t)(off + m0 + lr0) * INTER + col) =
                    make_float2(h0, h1);
            }
            if (m0 + lr1 < cnt) {
                float g2 = gacc[mi][ni][2], g3 = gacc[mi][ni][3];
                float h2 = g2 / (1.f + __expf(-g2)) * uacc[mi][ni][2];
                float h3 = g3 / (1.f + __expf(-g3)) * uacc[mi][ni][3];
                *(float2*)(d_hbuf + (size_t)(off + m0 + lr1) * INTER + col) =
                    make_float2(h2, h3);
            }
        }
    }
}

// ---------------------------------------------------------------------------
// GEMM2: y = h @ W2[e]; scatter out[token] += router_weight * y
// ---------------------------------------------------------------------------
__global__ __launch_bounds__(128)
void gemm2_kernel(const float* __restrict__ w2, float* __restrict__ out) {
    const int e   = blockIdx.z;
    const int cnt = d_cnt[e];
    const int m0  = blockIdx.x * BM;
    if (m0 >= cnt) return;
    const int n0  = blockIdx.y * BN;
    const int off = d_off[e];

    __shared__ uint32_t As[BM * AS_STRIDE];
    __shared__ uint32_t Ws[BK * WS_STRIDE];

    const int tid  = threadIdx.x;
    const int lane = tid & 31, warp = tid >> 5;
    const int wm = warp >> 1, wn = warp & 1;
    const int g = lane >> 2, tg = lane & 3;

    const float* aptr[4];
#pragma unroll
    for (int i = 0; i < 4; i++) {
        int f = tid + i * 128;
        int row = f >> 3;
        int gr = m0 + row;
        aptr[i] = (gr < cnt) ? (d_hbuf + (size_t)(off + gr) * INTER) : nullptr;
    }
    const float* wp = w2 + (size_t)e * INTER * HIDDEN + n0;

    float acc[2][8][4];
#pragma unroll
    for (int mi = 0; mi < 2; mi++)
#pragma unroll
        for (int ni = 0; ni < 8; ni++)
#pragma unroll
            for (int r = 0; r < 4; r++) acc[mi][ni][r] = 0.f;

    for (int k0 = 0; k0 < INTER; k0 += BK) {
#pragma unroll
        for (int i = 0; i < 4; i++) {
            int f = tid + i * 128;
            int row = f >> 3, col = (f & 7) * 4;
            float4 v = make_float4(0.f, 0.f, 0.f, 0.f);
            if (aptr[i]) v = *(const float4*)(aptr[i] + k0 + col);
            uint32_t* dst = &As[row * AS_STRIDE + col];
            dst[0] = f2tf32(v.x); dst[1] = f2tf32(v.y);
            dst[2] = f2tf32(v.z); dst[3] = f2tf32(v.w);
        }
#pragma unroll
        for (int i = 0; i < 8; i++) {
            int f = tid + i * 128;
            int row = f >> 5, col = (f & 31) * 4;
            const float4 v = *(const float4*)(wp + (size_t)(k0 + row) * HIDDEN + col);
            uint32_t* dw = &Ws[row * WS_STRIDE + col];
            dw[0] = f2tf32(v.x); dw[1] = f2tf32(v.y);
            dw[2] = f2tf32(v.z); dw[3] = f2tf32(v.w);
        }
        __syncthreads();

#pragma unroll
        for (int kk = 0; kk < BK; kk += 8) {
            uint32_t a[2][4];
#pragma unroll
            for (int mi = 0; mi < 2; mi++) {
                int rb = wm * 32 + mi * 16;
                a[mi][0] = As[(rb + g)     * AS_STRIDE + kk + tg];
                a[mi][1] = As[(rb + g + 8) * AS_STRIDE + kk + tg];
                a[mi][2] = As[(rb + g)     * AS_STRIDE + kk + tg + 4];
                a[mi][3] = As[(rb + g + 8) * AS_STRIDE + kk + tg + 4];
            }
#pragma unroll
            for (int ni = 0; ni < 8; ni++) {
                int cb = wn * 64 + ni * 8;
                uint32_t b0 = Ws[(kk + tg)     * WS_STRIDE + cb + g];
                uint32_t b1 = Ws[(kk + tg + 4) * WS_STRIDE + cb + g];
                mma_tf32(acc[0][ni], a[0], b0, b1);
                mma_tf32(acc[1][ni], a[1], b0, b1);
            }
        }
        __syncthreads();
    }

    // ---- epilogue: out[token] += w * y (top-k combine via atomics) ----
#pragma unroll
    for (int mi = 0; mi < 2; mi++) {
#pragma unroll
        for (int ni = 0; ni < 8; ni++) {
            int lr0 = wm * 32 + mi * 16 + g;
            int lr1 = lr0 + 8;
            int col = n0 + wn * 64 + ni * 8 + tg * 2;
            if (m0 + lr0 < cnt) {
                int   t  = d_tok[off + m0 + lr0];
                float wt = d_wgt[off + m0 + lr0];
                atomicAdd(&out[(size_t)t * HIDDEN + col],     wt * acc[mi][ni][0]);
                atomicAdd(&out[(size_t)t * HIDDEN + col + 1], wt * acc[mi][ni][1]);
            }
            if (m0 + lr1 < cnt) {
                int   t  = d_tok[off + m0 + lr1];
                float wt = d_wgt[off + m0 + lr1];
                atomicAdd(&out[(size_t)t * HIDDEN + col],     wt * acc[mi][ni][2]);
                atomicAdd(&out[(size_t)t * HIDDEN + col + 1], wt * acc[mi][ni][3]);
            }
        }
    }
}

// ---------------------------------------------------------------------------
// launch: route -> gemm1 (gate/up + swiglu) -> gemm2 (+combine)
// inputs (metadata order): x, expert_weights, w1, w2, w3, expert_indices
// ---------------------------------------------------------------------------
extern "C" void kernel_launch(void* const* d_in, const int* in_sizes, int n_in,
                              void* d_out, int out_size) {
    const float* x  = (const float*)d_in[0];
    const float* ew = (const float*)d_in[1];
    const float* w1 = (const float*)d_in[2];
    const float* w2 = (const float*)d_in[3];
    const float* w3 = (const float*)d_in[4];
    const int*   ei = (const int*)d_in[5];
    float* out = (float*)d_out;

    cudaMemsetAsync(out, 0, sizeof(float) * (size_t)TOKENS * HIDDEN, 0);
    route_kernel<<<1, 256>>>(ei, ew);

    dim3 g1(NPAIR / BM, INTER / BN, NEXP);    // m fastest -> L2 W-slab reuse
    gemm1_kernel<<<g1, 128>>>(x, w1, w3);

    dim3 g2(NPAIR / BM, HIDDEN / BN, NEXP);
    gemm2_kernel<<<g2, 128>>>(w2, out);
}